// round 2
// baseline (speedup 1.0000x reference)
#include <cuda_runtime.h>
#include <math.h>

#define NTOK 4096
#define BD 16      // q/k projection dim
#define CC 128     // value channels
#define BM 64      // query tile
#define BN 64      // key tile
#define NB 4       // batch

// scratch (allocation-free rule: __device__ globals)
__device__ __align__(16) float g_q[NB * NTOK * BD];
__device__ __align__(16) float g_k[NB * NTOK * BD];
__device__ __align__(16) float g_v[NB * NTOK * CC];

// ---------------------------------------------------------------------------
// q/k projection: q[b,n,d] = sum_c Wq[d,c] * x[b,c,n] + bq[d]
// grid (NTOK/256, B), 256 threads, one token per thread
// ---------------------------------------------------------------------------
__global__ void proj_qk_kernel(const float* __restrict__ x,
                               const float* __restrict__ Wq, const float* __restrict__ bq,
                               const float* __restrict__ Wk, const float* __restrict__ bk)
{
    __shared__ float sWq[16 * 64], sWk[16 * 64], sb[32];
    int tid = threadIdx.x;
    for (int e = tid; e < 1024; e += 256) { sWq[e] = Wq[e]; sWk[e] = Wk[e]; }
    if (tid < 16) { sb[tid] = bq[tid]; sb[16 + tid] = bk[tid]; }
    __syncthreads();

    int b = blockIdx.y;
    int n = blockIdx.x * 256 + tid;

    float xc[64];
#pragma unroll
    for (int c = 0; c < 64; ++c) xc[c] = x[((size_t)b * 64 + c) * NTOK + n];

    float* qo = g_q + ((size_t)b * NTOK + n) * BD;
    float* ko = g_k + ((size_t)b * NTOK + n) * BD;

#pragma unroll
    for (int d4 = 0; d4 < 4; ++d4) {
        float q[4], k[4];
#pragma unroll
        for (int r = 0; r < 4; ++r) { q[r] = sb[d4 * 4 + r]; k[r] = sb[16 + d4 * 4 + r]; }
#pragma unroll
        for (int c = 0; c < 64; ++c) {
#pragma unroll
            for (int r = 0; r < 4; ++r) {
                q[r] += sWq[(d4 * 4 + r) * 64 + c] * xc[c];
                k[r] += sWk[(d4 * 4 + r) * 64 + c] * xc[c];
            }
        }
        ((float4*)qo)[d4] = make_float4(q[0], q[1], q[2], q[3]);
        ((float4*)ko)[d4] = make_float4(k[0], k[1], k[2], k[3]);
    }
}

// ---------------------------------------------------------------------------
// v projection: v[b,n,c] = sum_c' Wv[c,c'] * xh[b,c',n] + bv[c]
// grid (NTOK/64, B), 256 threads: 64 tokens x 4 groups of 32 channels
// ---------------------------------------------------------------------------
__global__ void proj_v_kernel(const float* __restrict__ xh,
                              const float* __restrict__ Wv, const float* __restrict__ bv)
{
    __shared__ float Xs[128][64];   // 32 KB
    __shared__ float Wt[16][128];   //  8 KB (transposed chunk of Wv)
    int tid = threadIdx.x;
    int b = blockIdx.y;
    int n0 = blockIdx.x * 64;
    int nl = tid & 63;
    int g  = tid >> 6;

    for (int e = tid; e < 128 * 64; e += 256) {
        int c = e >> 6, nn = e & 63;
        Xs[c][nn] = xh[((size_t)b * 128 + c) * NTOK + n0 + nn];
    }

    float acc[32];
#pragma unroll
    for (int i = 0; i < 32; ++i) acc[i] = 0.f;

    for (int cc0 = 0; cc0 < 128; cc0 += 16) {
        __syncthreads();
        for (int e = tid; e < 16 * 128; e += 256) {
            int c = e >> 4, cp = e & 15;
            Wt[cp][c] = Wv[c * 128 + cc0 + cp];
        }
        __syncthreads();
#pragma unroll
        for (int cp = 0; cp < 16; ++cp) {
            float xv = Xs[cc0 + cp][nl];
            const float4* w4 = (const float4*)&Wt[cp][g * 32];
#pragma unroll
            for (int q = 0; q < 8; ++q) {
                float4 w = w4[q];
                acc[q * 4 + 0] += xv * w.x;
                acc[q * 4 + 1] += xv * w.y;
                acc[q * 4 + 2] += xv * w.z;
                acc[q * 4 + 3] += xv * w.w;
            }
        }
    }

    float* vo = g_v + ((size_t)b * NTOK + n0 + nl) * CC + g * 32;
#pragma unroll
    for (int q = 0; q < 8; ++q) {
        float4 o;
        o.x = acc[q * 4 + 0] + bv[g * 32 + q * 4 + 0];
        o.y = acc[q * 4 + 1] + bv[g * 32 + q * 4 + 1];
        o.z = acc[q * 4 + 2] + bv[g * 32 + q * 4 + 2];
        o.w = acc[q * 4 + 3] + bv[g * 32 + q * 4 + 3];
        ((float4*)vo)[q] = o;
    }
}

// ---------------------------------------------------------------------------
// flash attention: per (batch, 64-query tile), stream 64-key tiles.
// 256 threads = 16(ty: queries, strided) x 16(tx: keys / channel-slices)
// smem: Qs[64][17] Ks[64][17] Vs[64][128] Ps[64][65]; Os overlays Vs+Ps.
// ---------------------------------------------------------------------------
#define SMEM_FLOATS (64*17 + 64*17 + 64*128 + 64*65)

__global__ void flash_kernel(const float* __restrict__ xh,
                             const float* __restrict__ gamma,
                             float* __restrict__ out)
{
    extern __shared__ float sm[];
    float* Qs = sm;                 // [64][17]
    float* Ks = Qs + 64 * 17;       // [64][17]
    float* Vs = Ks + 64 * 17;       // [64][128]
    float* Ps = Vs + 64 * 128;      // [64][65]
    float* Os = Vs;                 // [128][65] overlay (33.3KB <= 49.4KB)

    int tid = threadIdx.x;
    int tx = tid & 15, ty = tid >> 4;
    int b  = blockIdx.y;
    int i0 = blockIdx.x * BM;

    const float* qb = g_q + (size_t)b * NTOK * BD;
    const float* kb = g_k + (size_t)b * NTOK * BD;
    const float* vb = g_v + (size_t)b * NTOK * CC;

    for (int e = tid; e < BM * BD; e += 256) {
        int i = e >> 4, d = e & 15;
        Qs[i * 17 + d] = qb[(size_t)(i0 + i) * BD + d];
    }

    float acc[4][8];
    float m[4], l[4];
#pragma unroll
    for (int ii = 0; ii < 4; ++ii) {
        m[ii] = -1e30f; l[ii] = 0.f;
#pragma unroll
        for (int c = 0; c < 8; ++c) acc[ii][c] = 0.f;
    }

    for (int j0 = 0; j0 < NTOK; j0 += BN) {
        __syncthreads();   // previous tile fully consumed
        for (int e = tid; e < BN * BD; e += 256) {
            int j = e >> 4, d = e & 15;
            Ks[j * 17 + d] = kb[(size_t)(j0 + j) * BD + d];
        }
        {
            const float4* vsrc = (const float4*)(vb + (size_t)j0 * CC);
            float4* vdst = (float4*)Vs;
#pragma unroll
            for (int r = 0; r < 8; ++r) vdst[tid + 256 * r] = vsrc[tid + 256 * r];
        }
        __syncthreads();

        // scores: i = ty + 16*ii, j = tx + 16*jj
        float s[4][4];
#pragma unroll
        for (int ii = 0; ii < 4; ++ii)
#pragma unroll
            for (int jj = 0; jj < 4; ++jj) s[ii][jj] = 0.f;
#pragma unroll
        for (int d = 0; d < 16; ++d) {
            float qv[4], kv[4];
#pragma unroll
            for (int ii = 0; ii < 4; ++ii) qv[ii] = Qs[(ty + 16 * ii) * 17 + d];
#pragma unroll
            for (int jj = 0; jj < 4; ++jj) kv[jj] = Ks[(tx + 16 * jj) * 17 + d];
#pragma unroll
            for (int ii = 0; ii < 4; ++ii)
#pragma unroll
                for (int jj = 0; jj < 4; ++jj)
                    s[ii][jj] += qv[ii] * kv[jj];
        }

        // online softmax update (row stats shared across the 16 tx lanes)
#pragma unroll
        for (int ii = 0; ii < 4; ++ii) {
            float mt = fmaxf(fmaxf(s[ii][0], s[ii][1]), fmaxf(s[ii][2], s[ii][3]));
#pragma unroll
            for (int off = 8; off >= 1; off >>= 1)
                mt = fmaxf(mt, __shfl_xor_sync(0xffffffffu, mt, off));
            float mn = fmaxf(m[ii], mt);
            float sc = __expf(m[ii] - mn);
            l[ii] *= sc;
#pragma unroll
            for (int c = 0; c < 8; ++c) acc[ii][c] *= sc;
            float rs = 0.f;
#pragma unroll
            for (int jj = 0; jj < 4; ++jj) {
                float p = __expf(s[ii][jj] - mn);
                Ps[(tx + 16 * jj) * 65 + ty + 16 * ii] = p;
                rs += p;
            }
#pragma unroll
            for (int off = 8; off >= 1; off >>= 1)
                rs += __shfl_xor_sync(0xffffffffu, rs, off);
            l[ii] += rs;
            m[ii] = mn;
        }
        __syncthreads();   // Ps visible

        // PV accumulation: 4 queries x 8 channels per thread
#pragma unroll 4
        for (int j = 0; j < BN; ++j) {
            float4 v0 = ((const float4*)Vs)[j * 32 + tx * 2];
            float4 v1 = ((const float4*)Vs)[j * 32 + tx * 2 + 1];
            float pv[4];
#pragma unroll
            for (int ii = 0; ii < 4; ++ii) pv[ii] = Ps[j * 65 + ty + 16 * ii];
#pragma unroll
            for (int ii = 0; ii < 4; ++ii) {
                acc[ii][0] += pv[ii] * v0.x; acc[ii][1] += pv[ii] * v0.y;
                acc[ii][2] += pv[ii] * v0.z; acc[ii][3] += pv[ii] * v0.w;
                acc[ii][4] += pv[ii] * v1.x; acc[ii][5] += pv[ii] * v1.y;
                acc[ii][6] += pv[ii] * v1.z; acc[ii][7] += pv[ii] * v1.w;
            }
        }
    }

    float g = gamma[0];
    __syncthreads();   // done reading Vs/Ps before Os overlay
#pragma unroll
    for (int ii = 0; ii < 4; ++ii) {
        float inv = g / l[ii];
        int i = ty + 16 * ii;
#pragma unroll
        for (int c = 0; c < 8; ++c)
            Os[(tx * 8 + c) * 65 + i] = acc[ii][c] * inv;
    }
    __syncthreads();
    for (int e = tid; e < CC * BM; e += 256) {
        int c = e >> 6, il = e & 63;
        size_t gi = ((size_t)b * CC + c) * NTOK + i0 + il;
        out[gi] = Os[c * 65 + il] + xh[gi];
    }
}

// ---------------------------------------------------------------------------
extern "C" void kernel_launch(void* const* d_in, const int* in_sizes, int n_in,
                              void* d_out, int out_size)
{
    const float* x     = (const float*)d_in[0];
    const float* xh    = (const float*)d_in[1];
    const float* Wq    = (const float*)d_in[2];
    const float* bq    = (const float*)d_in[3];
    const float* Wk    = (const float*)d_in[4];
    const float* bk    = (const float*)d_in[5];
    const float* Wv    = (const float*)d_in[6];
    const float* bv    = (const float*)d_in[7];
    const float* gamma = (const float*)d_in[8];
    float* out = (float*)d_out;

    (void)in_sizes; (void)n_in; (void)out_size;

    int smem_bytes = SMEM_FLOATS * (int)sizeof(float);   // 58112
    cudaFuncSetAttribute(flash_kernel, cudaFuncAttributeMaxDynamicSharedMemorySize, smem_bytes);

    proj_qk_kernel<<<dim3(NTOK / 256, NB), 256>>>(x, Wq, bq, Wk, bk);
    proj_v_kernel<<<dim3(NTOK / 64, NB), 256>>>(xh, Wv, bv);
    flash_kernel<<<dim3(NTOK / BM, NB), 256, smem_bytes>>>(xh, gamma, out);
}

// round 3
// speedup vs baseline: 1.0012x; 1.0012x over previous
#include <cuda_runtime.h>
#include <math.h>

#define NTOK 4096
#define BD 16      // q/k projection dim
#define CC 128     // value channels
#define BM 64      // query tile
#define BN 64      // key tile
#define NB 4       // batch

// scratch (allocation-free rule: __device__ globals)
__device__ __align__(16) float g_q[NB * NTOK * BD];
__device__ __align__(16) float g_k[NB * NTOK * BD];
__device__ __align__(16) float g_v[NB * NTOK * CC];

// ---------------------------------------------------------------------------
// q/k projection: q[b,n,d] = sum_c Wq[d,c] * x[b,c,n] + bq[d]
// grid (NTOK/256, B), 256 threads, one token per thread
// ---------------------------------------------------------------------------
__global__ void proj_qk_kernel(const float* __restrict__ x,
                               const float* __restrict__ Wq, const float* __restrict__ bq,
                               const float* __restrict__ Wk, const float* __restrict__ bk)
{
    __shared__ float sWq[16 * 64], sWk[16 * 64], sb[32];
    int tid = threadIdx.x;
    for (int e = tid; e < 1024; e += 256) { sWq[e] = Wq[e]; sWk[e] = Wk[e]; }
    if (tid < 16) { sb[tid] = bq[tid]; sb[16 + tid] = bk[tid]; }
    __syncthreads();

    int b = blockIdx.y;
    int n = blockIdx.x * 256 + tid;

    float xc[64];
#pragma unroll
    for (int c = 0; c < 64; ++c) xc[c] = x[((size_t)b * 64 + c) * NTOK + n];

    float* qo = g_q + ((size_t)b * NTOK + n) * BD;
    float* ko = g_k + ((size_t)b * NTOK + n) * BD;

#pragma unroll
    for (int d4 = 0; d4 < 4; ++d4) {
        float q[4], k[4];
#pragma unroll
        for (int r = 0; r < 4; ++r) { q[r] = sb[d4 * 4 + r]; k[r] = sb[16 + d4 * 4 + r]; }
#pragma unroll
        for (int c = 0; c < 64; ++c) {
#pragma unroll
            for (int r = 0; r < 4; ++r) {
                q[r] += sWq[(d4 * 4 + r) * 64 + c] * xc[c];
                k[r] += sWk[(d4 * 4 + r) * 64 + c] * xc[c];
            }
        }
        ((float4*)qo)[d4] = make_float4(q[0], q[1], q[2], q[3]);
        ((float4*)ko)[d4] = make_float4(k[0], k[1], k[2], k[3]);
    }
}

// ---------------------------------------------------------------------------
// v projection: v[b,n,c] = sum_c' Wv[c,c'] * xh[b,c',n] + bv[c]
// grid (NTOK/64, B), 256 threads: 64 tokens x 4 groups of 32 channels
// ---------------------------------------------------------------------------
__global__ void proj_v_kernel(const float* __restrict__ xh,
                              const float* __restrict__ Wv, const float* __restrict__ bv)
{
    __shared__ float Xs[128][64];   // 32 KB
    __shared__ float Wt[16][128];   //  8 KB (transposed chunk of Wv)
    int tid = threadIdx.x;
    int b = blockIdx.y;
    int n0 = blockIdx.x * 64;
    int nl = tid & 63;
    int g  = tid >> 6;

    for (int e = tid; e < 128 * 64; e += 256) {
        int c = e >> 6, nn = e & 63;
        Xs[c][nn] = xh[((size_t)b * 128 + c) * NTOK + n0 + nn];
    }

    float acc[32];
#pragma unroll
    for (int i = 0; i < 32; ++i) acc[i] = 0.f;

    for (int cc0 = 0; cc0 < 128; cc0 += 16) {
        __syncthreads();
        for (int e = tid; e < 16 * 128; e += 256) {
            int c = e >> 4, cp = e & 15;
            Wt[cp][c] = Wv[c * 128 + cc0 + cp];
        }
        __syncthreads();
#pragma unroll
        for (int cp = 0; cp < 16; ++cp) {
            float xv = Xs[cc0 + cp][nl];
            const float4* w4 = (const float4*)&Wt[cp][g * 32];
#pragma unroll
            for (int q = 0; q < 8; ++q) {
                float4 w = w4[q];
                acc[q * 4 + 0] += xv * w.x;
                acc[q * 4 + 1] += xv * w.y;
                acc[q * 4 + 2] += xv * w.z;
                acc[q * 4 + 3] += xv * w.w;
            }
        }
    }

    float* vo = g_v + ((size_t)b * NTOK + n0 + nl) * CC + g * 32;
#pragma unroll
    for (int q = 0; q < 8; ++q) {
        float4 o;
        o.x = acc[q * 4 + 0] + bv[g * 32 + q * 4 + 0];
        o.y = acc[q * 4 + 1] + bv[g * 32 + q * 4 + 1];
        o.z = acc[q * 4 + 2] + bv[g * 32 + q * 4 + 2];
        o.w = acc[q * 4 + 3] + bv[g * 32 + q * 4 + 3];
        ((float4*)vo)[q] = o;
    }
}

// ---------------------------------------------------------------------------
// flash attention: per (batch, 64-query tile), stream 64-key tiles.
// 256 threads = 16(ty: queries, strided) x 16(tx: keys / channel-slices)
// smem: Qs[64][17] Ks[64][17] Vs[64][128] Ps[64][65]; Os overlays Vs+Ps.
// ---------------------------------------------------------------------------
#define SMEM_FLOATS (64*17 + 64*17 + 64*128 + 64*65)

__global__ void flash_kernel(const float* __restrict__ xh,
                             const float* __restrict__ gamma,
                             float* __restrict__ out)
{
    extern __shared__ float sm[];
    float* Qs = sm;                 // [64][17]
    float* Ks = Qs + 64 * 17;       // [64][17]
    float* Vs = Ks + 64 * 17;       // [64][128]
    float* Ps = Vs + 64 * 128;      // [64][65]
    float* Os = Vs;                 // [128][65] overlay (33.3KB <= 49.4KB)

    int tid = threadIdx.x;
    int tx = tid & 15, ty = tid >> 4;
    int b  = blockIdx.y;
    int i0 = blockIdx.x * BM;

    const float* qb = g_q + (size_t)b * NTOK * BD;
    const float* kb = g_k + (size_t)b * NTOK * BD;
    const float* vb = g_v + (size_t)b * NTOK * CC;

    for (int e = tid; e < BM * BD; e += 256) {
        int i = e >> 4, d = e & 15;
        Qs[i * 17 + d] = qb[(size_t)(i0 + i) * BD + d];
    }

    float acc[4][8];
    float m[4], l[4];
#pragma unroll
    for (int ii = 0; ii < 4; ++ii) {
        m[ii] = -1e30f; l[ii] = 0.f;
#pragma unroll
        for (int c = 0; c < 8; ++c) acc[ii][c] = 0.f;
    }

    for (int j0 = 0; j0 < NTOK; j0 += BN) {
        __syncthreads();   // previous tile fully consumed
        for (int e = tid; e < BN * BD; e += 256) {
            int j = e >> 4, d = e & 15;
            Ks[j * 17 + d] = kb[(size_t)(j0 + j) * BD + d];
        }
        {
            const float4* vsrc = (const float4*)(vb + (size_t)j0 * CC);
            float4* vdst = (float4*)Vs;
#pragma unroll
            for (int r = 0; r < 8; ++r) vdst[tid + 256 * r] = vsrc[tid + 256 * r];
        }
        __syncthreads();

        // scores: i = ty + 16*ii, j = tx + 16*jj
        float s[4][4];
#pragma unroll
        for (int ii = 0; ii < 4; ++ii)
#pragma unroll
            for (int jj = 0; jj < 4; ++jj) s[ii][jj] = 0.f;
#pragma unroll
        for (int d = 0; d < 16; ++d) {
            float qv[4], kv[4];
#pragma unroll
            for (int ii = 0; ii < 4; ++ii) qv[ii] = Qs[(ty + 16 * ii) * 17 + d];
#pragma unroll
            for (int jj = 0; jj < 4; ++jj) kv[jj] = Ks[(tx + 16 * jj) * 17 + d];
#pragma unroll
            for (int ii = 0; ii < 4; ++ii)
#pragma unroll
                for (int jj = 0; jj < 4; ++jj)
                    s[ii][jj] += qv[ii] * kv[jj];
        }

        // online softmax update (row stats shared across the 16 tx lanes)
#pragma unroll
        for (int ii = 0; ii < 4; ++ii) {
            float mt = fmaxf(fmaxf(s[ii][0], s[ii][1]), fmaxf(s[ii][2], s[ii][3]));
#pragma unroll
            for (int off = 8; off >= 1; off >>= 1)
                mt = fmaxf(mt, __shfl_xor_sync(0xffffffffu, mt, off));
            float mn = fmaxf(m[ii], mt);
            float sc = __expf(m[ii] - mn);
            l[ii] *= sc;
#pragma unroll
            for (int c = 0; c < 8; ++c) acc[ii][c] *= sc;
            float rs = 0.f;
#pragma unroll
            for (int jj = 0; jj < 4; ++jj) {
                float p = __expf(s[ii][jj] - mn);
                Ps[(tx + 16 * jj) * 65 + ty + 16 * ii] = p;
                rs += p;
            }
#pragma unroll
            for (int off = 8; off >= 1; off >>= 1)
                rs += __shfl_xor_sync(0xffffffffu, rs, off);
            l[ii] += rs;
            m[ii] = mn;
        }
        __syncthreads();   // Ps visible

        // PV accumulation: 4 queries x 8 channels per thread
#pragma unroll 4
        for (int j = 0; j < BN; ++j) {
            float4 v0 = ((const float4*)Vs)[j * 32 + tx * 2];
            float4 v1 = ((const float4*)Vs)[j * 32 + tx * 2 + 1];
            float pv[4];
#pragma unroll
            for (int ii = 0; ii < 4; ++ii) pv[ii] = Ps[j * 65 + ty + 16 * ii];
#pragma unroll
            for (int ii = 0; ii < 4; ++ii) {
                acc[ii][0] += pv[ii] * v0.x; acc[ii][1] += pv[ii] * v0.y;
                acc[ii][2] += pv[ii] * v0.z; acc[ii][3] += pv[ii] * v0.w;
                acc[ii][4] += pv[ii] * v1.x; acc[ii][5] += pv[ii] * v1.y;
                acc[ii][6] += pv[ii] * v1.z; acc[ii][7] += pv[ii] * v1.w;
            }
        }
    }

    float g = gamma[0];
    __syncthreads();   // done reading Vs/Ps before Os overlay
#pragma unroll
    for (int ii = 0; ii < 4; ++ii) {
        float inv = g / l[ii];
        int i = ty + 16 * ii;
#pragma unroll
        for (int c = 0; c < 8; ++c)
            Os[(tx * 8 + c) * 65 + i] = acc[ii][c] * inv;
    }
    __syncthreads();
    for (int e = tid; e < CC * BM; e += 256) {
        int c = e >> 6, il = e & 63;
        size_t gi = ((size_t)b * CC + c) * NTOK + i0 + il;
        out[gi] = Os[c * 65 + il] + xh[gi];
    }
}

// ---------------------------------------------------------------------------
extern "C" void kernel_launch(void* const* d_in, const int* in_sizes, int n_in,
                              void* d_out, int out_size)
{
    const float* x     = (const float*)d_in[0];
    const float* xh    = (const float*)d_in[1];
    const float* Wq    = (const float*)d_in[2];
    const float* bq    = (const float*)d_in[3];
    const float* Wk    = (const float*)d_in[4];
    const float* bk    = (const float*)d_in[5];
    const float* Wv    = (const float*)d_in[6];
    const float* bv    = (const float*)d_in[7];
    const float* gamma = (const float*)d_in[8];
    float* out = (float*)d_out;

    (void)in_sizes; (void)n_in; (void)out_size;

    int smem_bytes = SMEM_FLOATS * (int)sizeof(float);   // 58112
    cudaFuncSetAttribute(flash_kernel, cudaFuncAttributeMaxDynamicSharedMemorySize, smem_bytes);

    proj_qk_kernel<<<dim3(NTOK / 256, NB), 256>>>(x, Wq, bq, Wk, bk);
    proj_v_kernel<<<dim3(NTOK / 64, NB), 256>>>(xh, Wv, bv);
    flash_kernel<<<dim3(NTOK / BM, NB), 256, smem_bytes>>>(xh, gamma, out);
}